// round 3
// baseline (speedup 1.0000x reference)
#include <cuda_runtime.h>
#include <math.h>

#define H      128
#define NMAX   50000
#define EMAX   800000
#define NT     4
#define ET     8
#define NM     (2 + ET)              // K, V, 8x Qt
#define PERM_LEN (NMAX + NT*64)

// ---------------- device scratch (no dynamic allocation allowed) ----------------
static __device__ float d_C[NT*ET*H*H];                 // 2 MB   combined W_Q @ W_edge^T
static __device__ float d_K[(size_t)NMAX*H];            // 25.6 MB
static __device__ float d_V[(size_t)NMAX*H];            // 25.6 MB
static __device__ float d_Qt[(size_t)NMAX*ET*H];        // 204.8 MB
static __device__ float d_scores[EMAX];
static __device__ int   d_cnt[NT];
static __device__ int   d_abase[NT+1];
static __device__ int   d_rankN[NMAX];
static __device__ int   d_perm[PERM_LEN];
static __device__ int   d_deg[NMAX];
static __device__ int   d_erank[EMAX];
static __device__ int   d_eoff[NMAX+1];
static __device__ int   d_es[EMAX];

// ---------------- small prep kernels ----------------
__global__ void k_init(int N) {
    int i = blockIdx.x * blockDim.x + threadIdx.x;
    if (i < NT) d_cnt[i] = 0;
    if (i < N)  d_deg[i] = 0;
    if (i < PERM_LEN) d_perm[i] = -1;
}

__global__ void k_histN(const int* __restrict__ ntype, int N) {
    int i = blockIdx.x * blockDim.x + threadIdx.x;
    if (i >= N) return;
    int t = ntype[i];
    d_rankN[i] = atomicAdd(&d_cnt[t], 1);
}

__global__ void k_histE(const int* __restrict__ ei, int E) {
    int e = blockIdx.x * blockDim.x + threadIdx.x;
    if (e >= E) return;
    int dst = ei[E + e];
    d_erank[e] = atomicAdd(&d_deg[dst], 1);
}

__global__ void k_prefix() {
    int a = 0;
    for (int t = 0; t < NT; t++) {
        d_abase[t] = a;
        a = (a + d_cnt[t] + 63) & ~63;   // 64-align each type segment
    }
    d_abase[NT] = a;
}

// single-block exclusive scan of d_deg -> d_eoff
__global__ void k_scan(int N) {
    __shared__ int warpsums[32];
    __shared__ int s_carry;
    int tid = threadIdx.x;
    int lane = tid & 31, wid = tid >> 5;
    if (tid == 0) s_carry = 0;
    __syncthreads();
    for (int base = 0; base < N; base += 1024) {
        int i = base + tid;
        int v = (i < N) ? d_deg[i] : 0;
        int x = v;
        #pragma unroll
        for (int o = 1; o < 32; o <<= 1) {
            int y = __shfl_up_sync(0xffffffffu, x, o);
            if (lane >= o) x += y;
        }
        if (lane == 31) warpsums[wid] = x;
        __syncthreads();
        if (wid == 0) {
            int s = warpsums[lane];
            #pragma unroll
            for (int o = 1; o < 32; o <<= 1) {
                int y = __shfl_up_sync(0xffffffffu, s, o);
                if (lane >= o) s += y;
            }
            warpsums[lane] = s;
        }
        __syncthreads();
        int pre = (wid > 0) ? warpsums[wid - 1] : 0;
        int incl = x + pre + s_carry;
        if (i < N) d_eoff[i] = incl - v;     // exclusive
        __syncthreads();
        if (tid == 1023) s_carry = incl;
        __syncthreads();
    }
    if (tid == 0) d_eoff[N] = s_carry;
}

__global__ void k_scatterN(const int* __restrict__ ntype, int N) {
    int i = blockIdx.x * blockDim.x + threadIdx.x;
    if (i >= N) return;
    int t = ntype[i];
    d_perm[d_abase[t] + d_rankN[i]] = i;
}

__global__ void k_scatterE(const int* __restrict__ ei, int E) {
    int e = blockIdx.x * blockDim.x + threadIdx.x;
    if (e >= E) return;
    int dst = ei[E + e];
    d_es[d_eoff[dst] + d_erank[e]] = e;
}

// ---------------- C[t][et] = W_Q[t] @ W_edge[et]^T ----------------
// smem: sQ[128*128] + sEt[128*129] (W_edge transposed, padded)
#define SMEM_C ((H*H + H*129) * 4)
__global__ void k_C(const float* __restrict__ WQ, const float* __restrict__ WE) {
    extern __shared__ float sm[];
    float* sQ  = sm;             // [k][j]
    float* sEt = sm + H*H;       // [j][i], pitch 129
    int b = blockIdx.x;
    int t = b >> 3, et = b & 7;
    const float4* q4 = (const float4*)(WQ + (size_t)t * H * H);
    const float4* e4 = (const float4*)(WE + (size_t)et * H * H);
    float4* sQ4 = (float4*)sQ;
    for (int idx = threadIdx.x; idx < H*H/4; idx += blockDim.x) {
        sQ4[idx] = q4[idx];
        float4 v = e4[idx];
        int i = idx >> 5;               // row of W_edge
        int j0 = (idx & 31) * 4;        // col
        sEt[(j0+0)*129 + i] = v.x;
        sEt[(j0+1)*129 + i] = v.y;
        sEt[(j0+2)*129 + i] = v.z;
        sEt[(j0+3)*129 + i] = v.w;
    }
    __syncthreads();
    for (int o = threadIdx.x; o < H*H; o += blockDim.x) {
        int k = o >> 7, i = o & 127;    // consecutive threads -> consecutive i
        float s = 0.f;
        #pragma unroll 8
        for (int j = 0; j < H; j++)
            s += sQ[k*H + j] * sEt[j*129 + i];
        d_C[(size_t)b * H * H + (size_t)k * H + i] = s;
    }
}

// ---------------- fused typed GEMM, m looped in-CTA ----------------
// m=0 -> K, m=1 -> V, m=2+et -> Qt[:, et]
// 128 threads, 64x128x128 tile per m, f32x2 packed FMA (full-rate FFMA on B300)
#define SMEM_B ((64*132 + H*H + 64) * 4)
__global__ void __launch_bounds__(128, 2) k_gemmB(
    const float* __restrict__ x,
    const float* __restrict__ WK,
    const float* __restrict__ WV)
{
    extern __shared__ float sm[];
    float* xs = sm;                         // [64][132]
    float* Ws = sm + 64*132;                // [128][128]
    int*   sperm = (int*)(sm + 64*132 + H*H); // [64]
    int row0 = blockIdx.x * 64;
    int total = d_abase[NT];
    if (row0 >= total) return;
    int t = 0;
    #pragma unroll
    for (int tt = 1; tt < NT; tt++) if (row0 >= d_abase[tt]) t = tt;

    int tid = threadIdx.x;
    int tx = tid & 15, ty = tid >> 4;
    int c0 = tx * 8, r0 = ty * 8;

    // cooperative perm preload, then gathered x-tile load (perm already resident)
    if (tid < 64) sperm[tid] = d_perm[row0 + tid];
    __syncthreads();
    for (int r = 0; r < 64; r++) {
        int node = sperm[r];
        xs[r*132 + tid] = (node >= 0) ? x[(size_t)node * H + tid] : 0.f;
    }

    for (int m = 0; m < NM; m++) {
        const float* W;
        if (m == 0)      W = WK + (size_t)t * H * H;
        else if (m == 1) W = WV + (size_t)t * H * H;
        else             W = d_C + ((size_t)(t * ET + (m - 2))) * H * H;

        __syncthreads();                    // previous compute done reading Ws
        {
            const float4* Wg = (const float4*)W;
            float4* Wsv = (float4*)Ws;
            #pragma unroll
            for (int i = 0; i < 32; i++) Wsv[tid + i*128] = Wg[tid + i*128];
        }
        __syncthreads();

        unsigned long long acc[8][4];
        #pragma unroll
        for (int i = 0; i < 8; i++)
            #pragma unroll
            for (int jp = 0; jp < 4; jp++) acc[i][jp] = 0ULL;

        #pragma unroll 4
        for (int k = 0; k < H; k++) {
            unsigned long long a2[8];
            #pragma unroll
            for (int i = 0; i < 8; i++) {
                float a = xs[(r0 + i)*132 + k];
                asm("mov.b64 %0, {%1, %2};" : "=l"(a2[i]) : "f"(a), "f"(a));
            }
            ulonglong2 bb0 = *(const ulonglong2*)&Ws[k*H + c0];
            ulonglong2 bb1 = *(const ulonglong2*)&Ws[k*H + c0 + 4];
            unsigned long long b2[4] = { bb0.x, bb0.y, bb1.x, bb1.y };
            #pragma unroll
            for (int i = 0; i < 8; i++) {
                #pragma unroll
                for (int jp = 0; jp < 4; jp++)
                    asm("fma.rn.f32x2 %0, %1, %2, %0;"
                        : "+l"(acc[i][jp]) : "l"(a2[i]), "l"(b2[jp]));
            }
        }

        #pragma unroll
        for (int i = 0; i < 8; i++) {
            int node = sperm[r0 + i];
            if (node < 0) continue;
            float* dst;
            if (m == 0)      dst = d_K + (size_t)node * H;
            else if (m == 1) dst = d_V + (size_t)node * H;
            else             dst = d_Qt + ((size_t)node * ET + (m - 2)) * H;
            *(ulonglong2*)&dst[c0]     = make_ulonglong2(acc[i][0], acc[i][1]);
            *(ulonglong2*)&dst[c0 + 4] = make_ulonglong2(acc[i][2], acc[i][3]);
        }
    }
}

// ---------------- per-edge scores: K[src] . Qt[dst, et] ----------------
__global__ void k_score(const int* __restrict__ ei, const int* __restrict__ etype,
                        const float* __restrict__ mu, int E)
{
    int g = blockIdx.x * blockDim.x + threadIdx.x;
    int w = g >> 5;
    if (w >= E) return;
    int lane = threadIdx.x & 31;
    int src = ei[w];
    int dst = ei[E + w];
    int et  = etype[w];
    const float4 kk = ((const float4*)(d_K  + (size_t)src * H))[lane];
    const float4 qq = ((const float4*)(d_Qt + ((size_t)dst * ET + et) * H))[lane];
    float p = kk.x*qq.x + kk.y*qq.y + kk.z*qq.z + kk.w*qq.w;
    #pragma unroll
    for (int o = 16; o > 0; o >>= 1) p += __shfl_xor_sync(0xffffffffu, p, o);
    if (lane == 0) {
        const float inv_scale = 0.08838834764831845f;  // 1/sqrt(128)
        d_scores[w] = (p * inv_scale) * mu[et];
    }
}

// ---------------- warp-per-dst: softmax + weighted V sum (atomic-free) ----------------
__global__ void k_out(const int* __restrict__ ei, float* __restrict__ out, int N)
{
    int g = (blockIdx.x * blockDim.x + threadIdx.x) >> 5;
    if (g >= N) return;
    int lane = threadIdx.x & 31;
    int s0 = d_eoff[g], s1 = d_eoff[g + 1];

    // pass 1: segment max
    float mloc = -1e9f;
    for (int i = s0 + lane; i < s1; i += 32)
        mloc = fmaxf(mloc, d_scores[d_es[i]]);
    #pragma unroll
    for (int o = 16; o > 0; o >>= 1)
        mloc = fmaxf(mloc, __shfl_xor_sync(0xffffffffu, mloc, o));

    // pass 2: exp once per edge (per-lane), broadcast via shfl during V accumulation
    float ax = 0.f, ay = 0.f, az = 0.f, aw = 0.f;
    float ssum = 0.f;
    for (int base = s0; base < s1; base += 32) {
        int i = base + lane;
        int   e_l = 0, src_l = 0;
        float a_l = 0.f;
        if (i < s1) {
            e_l = d_es[i];
            src_l = ei[e_l];
            a_l = expf(d_scores[e_l] - mloc);
        }
        ssum += a_l;
        int cnt = min(32, s1 - base);
        for (int j = 0; j < cnt; j++) {
            float a  = __shfl_sync(0xffffffffu, a_l, j);
            int  src = __shfl_sync(0xffffffffu, src_l, j);
            float4 v = ((const float4*)(d_V + (size_t)src * H))[lane];
            ax += a * v.x; ay += a * v.y; az += a * v.z; aw += a * v.w;
        }
    }
    #pragma unroll
    for (int o = 16; o > 0; o >>= 1) ssum += __shfl_xor_sync(0xffffffffu, ssum, o);
    float inv = 1.f / (ssum + 1e-10f);
    ((float4*)(out + (size_t)g * H))[lane] = make_float4(ax*inv, ay*inv, az*inv, aw*inv);
}

// ---------------- launch ----------------
extern "C" void kernel_launch(void* const* d_in, const int* in_sizes, int n_in,
                              void* d_out, int out_size)
{
    const float* x     = (const float*)d_in[0];
    const int*   ei    = (const int*)  d_in[1];   // [2, E] row-major: src then dst
    const int*   etype = (const int*)  d_in[2];
    const int*   ntype = (const int*)  d_in[3];
    const float* WQ    = (const float*)d_in[4];
    const float* WK    = (const float*)d_in[5];
    const float* WV    = (const float*)d_in[6];
    const float* WE    = (const float*)d_in[7];
    const float* mu    = (const float*)d_in[8];
    int N = in_sizes[0] / H;
    int E = in_sizes[1] / 2;

    cudaFuncSetAttribute(k_C,     cudaFuncAttributeMaxDynamicSharedMemorySize, SMEM_C);
    cudaFuncSetAttribute(k_gemmB, cudaFuncAttributeMaxDynamicSharedMemorySize, SMEM_B);

    k_init<<<(PERM_LEN + 255)/256, 256>>>(N);
    k_histN<<<(N + 255)/256, 256>>>(ntype, N);
    k_histE<<<(E + 255)/256, 256>>>(ei, E);
    k_prefix<<<1, 1>>>();
    k_scan<<<1, 1024>>>(N);
    k_scatterN<<<(N + 255)/256, 256>>>(ntype, N);
    k_scatterE<<<(E + 255)/256, 256>>>(ei, E);
    k_C<<<NT*ET, 256, SMEM_C>>>(WQ, WE);
    k_gemmB<<<(NMAX + NT*64 + 63)/64, 128, SMEM_B>>>(x, WK, WV);
    k_score<<<(E + 7)/8, 256>>>(ei, etype, mu, E);
    k_out<<<(N + 7)/8, 256>>>(ei, (float*)d_out, N);
}